// round 3
// baseline (speedup 1.0000x reference)
#include <cuda_runtime.h>
#include <cuda_bf16.h>
#include <limits.h>
#include <math.h>

#define NMAX 40000
#define EMAX 320000
#define D 128
#define KE 80   // edge K padded 73 -> 80 (5 k-steps of 16)

// ---------------- scratch (device globals; no allocations allowed) ----------
__device__ __nv_bfloat16 g_xhi[NMAX * D], g_xlo[NMAX * D];
__device__ __nv_bfloat16 g_pehi[(size_t)EMAX * KE], g_pelo[(size_t)EMAX * KE];
__device__ __nv_bfloat16 g_wnhi[2][4][D * D], g_wnlo[2][4][D * D];   // transposed [n][k]
__device__ __nv_bfloat16 g_wehi[2][D * KE], g_welo[2][D * KE];       // transposed [n][k]
__device__ float g_q[NMAX * D];
__device__ float g_k[NMAX * D];
__device__ float g_v[NMAX * D];
__device__ float g_s[NMAX * D];
__device__ float g_agg[NMAX * D];
__device__ float g_den[NMAX * 4];
__device__ int   g_m[NMAX * 4];
__device__ float g_e[(size_t)EMAX * D];
__device__ float g_score[EMAX * 4];
__device__ int   g_nid64;
__device__ int   g_ei64;

// ordered-int encoding for float atomicMax
__device__ __forceinline__ int fkey(float f) {
    int x = __float_as_int(f);
    return x < 0 ? (x ^ 0x7fffffff) : x;
}
__device__ __forceinline__ float fdecode(int k) {
    int x = k < 0 ? (k ^ 0x7fffffff) : k;
    return __int_as_float(x);
}
__device__ __forceinline__ int ld_idx(const void* p, long long i, int is64) {
    return is64 ? (int)((const long long*)p)[i] : ((const int*)p)[i];
}

// bf16 hi/lo split
__device__ __forceinline__ void split_bf(float v, __nv_bfloat16& h, __nv_bfloat16& l) {
    h = __float2bfloat16(v);
    l = __float2bfloat16(v - __bfloat162float(h));
}

// mma.sync m16n8k16 bf16, fp32 accum
__device__ __forceinline__ void mma_bf16(float* d, const unsigned* a, unsigned b0, unsigned b1) {
    asm volatile(
        "mma.sync.aligned.m16n8k16.row.col.f32.bf16.bf16.f32 "
        "{%0,%1,%2,%3}, {%4,%5,%6,%7}, {%8,%9}, {%0,%1,%2,%3};"
        : "+f"(d[0]), "+f"(d[1]), "+f"(d[2]), "+f"(d[3])
        : "r"(a[0]), "r"(a[1]), "r"(a[2]), "r"(a[3]), "r"(b0), "r"(b1));
}

// ---------------- index dtype detection -------------------------------------
__global__ void k_detect_nid(const int* __restrict__ p) {
    int v = p[1 + 2 * threadIdx.x];
    int any = __syncthreads_or(v != 0);
    if (threadIdx.x == 0) g_nid64 = (any == 0) ? 1 : 0;
}
__global__ void k_detect_ei(const int* __restrict__ p) {
    int v = p[1 + 2 * threadIdx.x];
    int any = __syncthreads_or(v != 0);
    if (threadIdx.x == 0) g_ei64 = (any == 0) ? 1 : 0;
}

// ---------------- gather x = memory_table[n_id] -> bf16 hi/lo ---------------
__global__ void k_gather(const float* __restrict__ mem, const void* __restrict__ n_id, int N) {
    int idx = blockIdx.x * blockDim.x + threadIdx.x;
    if (idx >= N * 64) return;                  // one thread per 2 floats
    int i = idx >> 6, c2 = idx & 63;
    int node = ld_idx(n_id, i, g_nid64);
    float2 v = ((const float2*)(mem + (size_t)node * D))[c2];
    __nv_bfloat16 h0, l0, h1, l1;
    split_bf(v.x, h0, l0);
    split_bf(v.y, h1, l1);
    ((__nv_bfloat162*)g_xhi)[(size_t)i * 64 + c2] = __halves2bfloat162(h0, h1);
    ((__nv_bfloat162*)g_xlo)[(size_t)i * 64 + c2] = __halves2bfloat162(l0, l1);
}

// ---------------- pe built directly as bf16 hi/lo (K padded to 80) ----------
__global__ void k_prep_pe(const float* __restrict__ ea, const float* __restrict__ et, int E) {
    int idx = blockIdx.x * blockDim.x + threadIdx.x;
    if (idx >= E * KE) return;
    int e = idx / KE, k = idx - e * KE;
    float val = 0.f;
    if (k < 3)       val = ea[e * 66 + k];
    else if (k < 65) val = ea[e * 66 + k + 1];
    else if (k < 73) {
        int t = (int)ea[e * 66 + 3];
        val = et[t * 8 + (k - 65)];
    }
    __nv_bfloat16 h, l;
    split_bf(val, h, l);
    g_pehi[idx] = h;
    g_pelo[idx] = l;
}

// ---------------- transpose + split all weights -----------------------------
__global__ void k_split_w(
    const float* __restrict__ Wq1, const float* __restrict__ Wk1,
    const float* __restrict__ Wv1, const float* __restrict__ Ws1,
    const float* __restrict__ Wq2, const float* __restrict__ Wk2,
    const float* __restrict__ Wv2, const float* __restrict__ Ws2,
    const float* __restrict__ We1, const float* __restrict__ We2)
{
    const float* tab[8] = {Wq1, Wk1, Wv1, Ws1, Wq2, Wk2, Wv2, Ws2};
    const float* tabe[2] = {We1, We2};
    int idx = blockIdx.x * blockDim.x + threadIdx.x;
    const int NODE_TOT = 2 * 4 * D * D;
    if (idx < NODE_TOT) {
        int layer = idx / (4 * D * D);
        int rem = idx % (4 * D * D);
        int w = rem / (D * D);
        int rem2 = rem % (D * D);
        int n = rem2 / D, k = rem2 % D;
        float v = tab[layer * 4 + w][k * D + n];
        __nv_bfloat16 h, l;
        split_bf(v, h, l);
        g_wnhi[layer][w][n * D + k] = h;
        g_wnlo[layer][w][n * D + k] = l;
    } else if (idx < NODE_TOT + 2 * D * KE) {
        int r = idx - NODE_TOT;
        int layer = r / (D * KE);
        int rem = r % (D * KE);
        int n = rem / KE, k = rem % KE;
        float v = (k < 73) ? tabe[layer][k * D + n] : 0.f;
        __nv_bfloat16 h, l;
        split_bf(v, h, l);
        g_wehi[layer][n * KE + k] = h;
        g_welo[layer][n * KE + k] = l;
    }
}

// ---------------- node GEMM (bf16x3 mma): q,k,v,s = x @ W + b ---------------
// block = 256 thr = 8 warps; warp covers 16 rows x 128 cols; K=128 (8 ksteps)
__global__ __launch_bounds__(256) void k_ngemm(int layer, int M,
    const float* __restrict__ bq, const float* __restrict__ bk,
    const float* __restrict__ bv, const float* __restrict__ bs)
{
    int tid = threadIdx.x, wid = tid >> 5, lane = tid & 31;
    int g = lane >> 2, q4 = lane & 3;
    int r0 = blockIdx.x * 128 + wid * 16 + g;
    int r1 = r0 + 8;
    bool v0 = r0 < M, v1 = r1 < M;
    const unsigned* Ah = (const unsigned*)g_xhi;
    const unsigned* Al = (const unsigned*)g_xlo;
    const float* bias[4] = {bq, bk, bv, bs};
    float* Cp[4] = {g_q, g_k, g_v, g_s};

    for (int w = 0; w < 4; w++) {
        const unsigned* Bh = (const unsigned*)g_wnhi[layer][w];
        const unsigned* Bl = (const unsigned*)g_wnlo[layer][w];
        float acc[16][4];
#pragma unroll
        for (int i = 0; i < 16; i++) {
            acc[i][0] = 0.f; acc[i][1] = 0.f; acc[i][2] = 0.f; acc[i][3] = 0.f;
        }
        for (int ks = 0; ks < 8; ks++) {
            size_t ai0 = (size_t)r0 * 64 + ks * 8 + q4;
            size_t ai1 = (size_t)r1 * 64 + ks * 8 + q4;
            unsigned ah[4], al[4];
            ah[0] = v0 ? __ldg(Ah + ai0) : 0u;
            ah[1] = v1 ? __ldg(Ah + ai1) : 0u;
            ah[2] = v0 ? __ldg(Ah + ai0 + 4) : 0u;
            ah[3] = v1 ? __ldg(Ah + ai1 + 4) : 0u;
            al[0] = v0 ? __ldg(Al + ai0) : 0u;
            al[1] = v1 ? __ldg(Al + ai1) : 0u;
            al[2] = v0 ? __ldg(Al + ai0 + 4) : 0u;
            al[3] = v1 ? __ldg(Al + ai1 + 4) : 0u;
#pragma unroll
            for (int nt = 0; nt < 16; nt++) {
                int bi = (nt * 8 + g) * 64 + ks * 8 + q4;
                unsigned bh0 = __ldg(Bh + bi), bh1 = __ldg(Bh + bi + 4);
                unsigned bl0 = __ldg(Bl + bi), bl1 = __ldg(Bl + bi + 4);
                mma_bf16(acc[nt], ah, bh0, bh1);
                mma_bf16(acc[nt], al, bh0, bh1);
                mma_bf16(acc[nt], ah, bl0, bl1);
            }
        }
#pragma unroll
        for (int nt = 0; nt < 16; nt++) {
            int n = nt * 8 + q4 * 2;
            float b0 = __ldg(bias[w] + n), b1 = __ldg(bias[w] + n + 1);
            if (v0) {
                float2 o = make_float2(acc[nt][0] + b0, acc[nt][1] + b1);
                *(float2*)(Cp[w] + (size_t)r0 * D + n) = o;
            }
            if (v1) {
                float2 o = make_float2(acc[nt][2] + b0, acc[nt][3] + b1);
                *(float2*)(Cp[w] + (size_t)r1 * D + n) = o;
            }
        }
    }
}

// ---------------- edge GEMM (bf16x3 mma): e = pe @ We -----------------------
__global__ __launch_bounds__(256) void k_egemm(int layer, int E) {
    int tid = threadIdx.x, wid = tid >> 5, lane = tid & 31;
    int g = lane >> 2, q4 = lane & 3;
    int r0 = blockIdx.x * 128 + wid * 16 + g;
    int r1 = r0 + 8;
    bool v0 = r0 < E, v1 = r1 < E;
    const unsigned* Ah = (const unsigned*)g_pehi;
    const unsigned* Al = (const unsigned*)g_pelo;
    const unsigned* Bh = (const unsigned*)g_wehi[layer];
    const unsigned* Bl = (const unsigned*)g_welo[layer];

    float acc[16][4];
#pragma unroll
    for (int i = 0; i < 16; i++) {
        acc[i][0] = 0.f; acc[i][1] = 0.f; acc[i][2] = 0.f; acc[i][3] = 0.f;
    }
    for (int ks = 0; ks < 5; ks++) {
        size_t ai0 = (size_t)r0 * 40 + ks * 8 + q4;
        size_t ai1 = (size_t)r1 * 40 + ks * 8 + q4;
        unsigned ah[4], al[4];
        ah[0] = v0 ? __ldg(Ah + ai0) : 0u;
        ah[1] = v1 ? __ldg(Ah + ai1) : 0u;
        ah[2] = v0 ? __ldg(Ah + ai0 + 4) : 0u;
        ah[3] = v1 ? __ldg(Ah + ai1 + 4) : 0u;
        al[0] = v0 ? __ldg(Al + ai0) : 0u;
        al[1] = v1 ? __ldg(Al + ai1) : 0u;
        al[2] = v0 ? __ldg(Al + ai0 + 4) : 0u;
        al[3] = v1 ? __ldg(Al + ai1 + 4) : 0u;
#pragma unroll
        for (int nt = 0; nt < 16; nt++) {
            int bi = (nt * 8 + g) * 40 + ks * 8 + q4;
            unsigned bh0 = __ldg(Bh + bi), bh1 = __ldg(Bh + bi + 4);
            unsigned bl0 = __ldg(Bl + bi), bl1 = __ldg(Bl + bi + 4);
            mma_bf16(acc[nt], ah, bh0, bh1);
            mma_bf16(acc[nt], al, bh0, bh1);
            mma_bf16(acc[nt], ah, bl0, bl1);
        }
    }
#pragma unroll
    for (int nt = 0; nt < 16; nt++) {
        int n = nt * 8 + q4 * 2;
        if (v0) {
            float2 o = make_float2(acc[nt][0], acc[nt][1]);
            *(float2*)(g_e + (size_t)r0 * D + n) = o;
        }
        if (v1) {
            float2 o = make_float2(acc[nt][2], acc[nt][3]);
            *(float2*)(g_e + (size_t)r1 * D + n) = o;
        }
    }
}

// ---------------- per-layer init: agg=0, den=0, m=-inf ----------------------
__global__ void k_init(int N) {
    int idx = blockIdx.x * blockDim.x + threadIdx.x;
    if (idx < N * D) g_agg[idx] = 0.f;
    if (idx < N * 4) { g_den[idx] = 0.f; g_m[idx] = INT_MIN; }
}

// ---------------- scores + segment max (warp per edge) ----------------------
__global__ void k_score(const void* __restrict__ ei, int E) {
    int gt = blockIdx.x * blockDim.x + threadIdx.x;
    int ed = gt >> 5;
    if (ed >= E) return;
    int lane = gt & 31;
    int is64 = g_ei64;
    int src = ld_idx(ei, ed, is64);
    int dst = ld_idx(ei, (long long)E + ed, is64);
    float4 q  = ((const float4*)(g_q + (size_t)dst * D))[lane];
    float4 kk = ((const float4*)(g_k + (size_t)src * D))[lane];
    float4 ev = ((const float4*)(g_e + (size_t)ed  * D))[lane];
    float s = q.x * (kk.x + ev.x) + q.y * (kk.y + ev.y)
            + q.z * (kk.z + ev.z) + q.w * (kk.w + ev.w);
    s += __shfl_xor_sync(0xffffffffu, s, 1);
    s += __shfl_xor_sync(0xffffffffu, s, 2);
    s += __shfl_xor_sync(0xffffffffu, s, 4);
    if ((lane & 7) == 0) {
        int h = lane >> 3;
        float sc = s * 0.1767766953f;
        g_score[ed * 4 + h] = sc;
        atomicMax(&g_m[dst * 4 + h], fkey(sc));
    }
}

// ---------------- exp(score - m) + segment denom ----------------------------
__global__ void k_ex(const void* __restrict__ ei, int E) {
    int idx = blockIdx.x * blockDim.x + threadIdx.x;
    if (idx >= E * 4) return;
    int ed = idx >> 2, h = idx & 3;
    int dst = ld_idx(ei, (long long)E + ed, g_ei64);
    float mm = fdecode(g_m[dst * 4 + h]);
    float ex = expf(g_score[idx] - mm);
    g_score[idx] = ex;
    atomicAdd(&g_den[dst * 4 + h], ex);
}

// ---------------- weighted scatter-add of v ---------------------------------
__global__ void k_agg(const void* __restrict__ ei, int E) {
    int idx = blockIdx.x * blockDim.x + threadIdx.x;
    if (idx >= E * 32) return;
    int ed = idx >> 5, c4 = idx & 31;
    int is64 = g_ei64;
    int src = ld_idx(ei, ed, is64);
    int dst = ld_idx(ei, (long long)E + ed, is64);
    int h = c4 >> 3;
    float alpha = g_score[ed * 4 + h] / (g_den[dst * 4 + h] + 1e-16f);
    float4 v  = ((const float4*)(g_v + (size_t)src * D))[c4];
    float4 ev = ((const float4*)(g_e + (size_t)ed  * D))[c4];
    float* a = g_agg + (size_t)dst * D + c4 * 4;
    atomicAdd(a + 0, (v.x + ev.x) * alpha);
    atomicAdd(a + 1, (v.y + ev.y) * alpha);
    atomicAdd(a + 2, (v.z + ev.z) * alpha);
    atomicAdd(a + 3, (v.w + ev.w) * alpha);
}

// ---------------- out = agg + skip; relu -> bf16 hi/lo x, else -> d_out -----
__global__ void k_final(float* __restrict__ out, int N, int relu) {
    int idx = blockIdx.x * blockDim.x + threadIdx.x;
    if (idx >= N * 32) return;
    int i = idx >> 5, c4 = idx & 31;
    float4 a = ((const float4*)(g_agg + (size_t)i * D))[c4];
    float4 s = ((const float4*)(g_s + (size_t)i * D))[c4];
    float4 o = make_float4(a.x + s.x, a.y + s.y, a.z + s.z, a.w + s.w);
    if (relu) {
        o.x = fmaxf(o.x, 0.f); o.y = fmaxf(o.y, 0.f);
        o.z = fmaxf(o.z, 0.f); o.w = fmaxf(o.w, 0.f);
        __nv_bfloat16 h0, l0, h1, l1, h2, l2, h3, l3;
        split_bf(o.x, h0, l0); split_bf(o.y, h1, l1);
        split_bf(o.z, h2, l2); split_bf(o.w, h3, l3);
        size_t base = (size_t)i * 64 + c4 * 2;
        ((__nv_bfloat162*)g_xhi)[base]     = __halves2bfloat162(h0, h1);
        ((__nv_bfloat162*)g_xhi)[base + 1] = __halves2bfloat162(h2, h3);
        ((__nv_bfloat162*)g_xlo)[base]     = __halves2bfloat162(l0, l1);
        ((__nv_bfloat162*)g_xlo)[base + 1] = __halves2bfloat162(l2, l3);
    } else {
        ((float4*)(out + (size_t)i * D))[c4] = o;
    }
}

// ---------------- launch -----------------------------------------------------
extern "C" void kernel_launch(void* const* d_in, const int* in_sizes, int n_in,
                              void* d_out, int out_size) {
    const float* mem    = (const float*)d_in[0];
    const float* ea     = (const float*)d_in[1];
    const float* et_emb = (const float*)d_in[2];
    const float* W1[5]  = {(const float*)d_in[3], (const float*)d_in[4], (const float*)d_in[5],
                           (const float*)d_in[6], (const float*)d_in[7]};   // Wq,Wk,Wv,We,Ws
    const float* b1[4]  = {(const float*)d_in[8], (const float*)d_in[9],
                           (const float*)d_in[10], (const float*)d_in[11]};
    const float* W2[5]  = {(const float*)d_in[12], (const float*)d_in[13], (const float*)d_in[14],
                           (const float*)d_in[15], (const float*)d_in[16]};
    const float* b2[4]  = {(const float*)d_in[17], (const float*)d_in[18],
                           (const float*)d_in[19], (const float*)d_in[20]};
    const void* n_id = d_in[21];
    const void* ei   = d_in[22];
    float* out = (float*)d_out;

    int N = in_sizes[21];
    int E = in_sizes[22] / 2;
    if (N > NMAX) N = NMAX;
    if (E > EMAX) E = EMAX;

    const int T = 256;
    k_detect_nid<<<1, 1024>>>((const int*)n_id);
    k_detect_ei<<<1, 1024>>>((const int*)ei);
    k_gather<<<(N * 64 + T - 1) / T, T>>>(mem, n_id, N);
    k_prep_pe<<<(E * KE + T - 1) / T, T>>>(ea, et_emb, E);
    {
        int tot = 2 * 4 * D * D + 2 * D * KE;
        // node weights order: Wq,Wk,Wv,Ws ; edge: We
        k_split_w<<<(tot + T - 1) / T, T>>>(W1[0], W1[1], W1[2], W1[4],
                                            W2[0], W2[1], W2[2], W2[4],
                                            W1[3], W2[3]);
    }

    int gN = (N + 127) / 128;
    int gE = (E + 127) / 128;

    // ---- layer 1 ----
    k_ngemm<<<gN, 256>>>(0, N, b1[0], b1[1], b1[2], b1[3]);
    k_egemm<<<gE, 256>>>(0, E);
    k_init<<<(N * D + T - 1) / T, T>>>(N);
    k_score<<<(E * 32 + T - 1) / T, T>>>(ei, E);
    k_ex<<<(E * 4 + T - 1) / T, T>>>(ei, E);
    k_agg<<<(E * 32 + T - 1) / T, T>>>(ei, E);
    k_final<<<(N * 32 + T - 1) / T, T>>>(out, N, 1);

    // ---- layer 2 ----
    k_ngemm<<<gN, 256>>>(1, N, b2[0], b2[1], b2[2], b2[3]);
    k_egemm<<<gE, 256>>>(1, E);
    k_init<<<(N * D + T - 1) / T, T>>>(N);
    k_score<<<(E * 32 + T - 1) / T, T>>>(ei, E);
    k_ex<<<(E * 4 + T - 1) / T, T>>>(ei, E);
    k_agg<<<(E * 32 + T - 1) / T, T>>>(ei, E);
    k_final<<<(N * 32 + T - 1) / T, T>>>(out, N, 0);
}

// round 4
// speedup vs baseline: 1.5127x; 1.5127x over previous
#include <cuda_runtime.h>
#include <cuda_bf16.h>
#include <limits.h>
#include <math.h>

#define NMAX 40000
#define EMAX 320000
#define D 128
#define KE 80            // edge K padded 73 -> 80 (5 k-steps of 16)
#define NSTR 136         // node smem row stride in bf16 (272B)
#define ESTR 88          // edge smem row stride in bf16 (176B)

// ---------------- scratch (device globals; no allocations allowed) ----------
__device__ __nv_bfloat16 g_xhi[NMAX * D], g_xlo[NMAX * D];
__device__ __nv_bfloat16 g_pehi[(size_t)EMAX * KE], g_pelo[(size_t)EMAX * KE];
__device__ __nv_bfloat16 g_wnhi[2][4][D * D], g_wnlo[2][4][D * D];   // [n][k]
__device__ __nv_bfloat16 g_wehi[2][D * KE], g_welo[2][D * KE];       // [n][k]
__device__ float g_q[NMAX * D];
__device__ float g_k[NMAX * D];
__device__ float g_v[NMAX * D];
__device__ float g_s[NMAX * D];
__device__ float g_agg[NMAX * D];
__device__ float g_den[NMAX * 4];
__device__ int   g_m[NMAX * 4];
__device__ float g_e[(size_t)EMAX * D];
__device__ float g_score[EMAX * 4];
__device__ int   g_nid64;
__device__ int   g_ei64;

// ordered-int encoding for float atomicMax
__device__ __forceinline__ int fkey(float f) {
    int x = __float_as_int(f);
    return x < 0 ? (x ^ 0x7fffffff) : x;
}
__device__ __forceinline__ float fdecode(int k) {
    int x = k < 0 ? (k ^ 0x7fffffff) : k;
    return __int_as_float(x);
}
__device__ __forceinline__ int ld_idx(const void* p, long long i, int is64) {
    return is64 ? (int)((const long long*)p)[i] : ((const int*)p)[i];
}
__device__ __forceinline__ void split_bf(float v, __nv_bfloat16& h, __nv_bfloat16& l) {
    h = __float2bfloat16(v);
    l = __float2bfloat16(v - __bfloat162float(h));
}
__device__ __forceinline__ void mma_bf16(float* d, const unsigned* a, unsigned b0, unsigned b1) {
    asm volatile(
        "mma.sync.aligned.m16n8k16.row.col.f32.bf16.bf16.f32 "
        "{%0,%1,%2,%3}, {%4,%5,%6,%7}, {%8,%9}, {%0,%1,%2,%3};"
        : "+f"(d[0]), "+f"(d[1]), "+f"(d[2]), "+f"(d[3])
        : "r"(a[0]), "r"(a[1]), "r"(a[2]), "r"(a[3]), "r"(b0), "r"(b1));
}
__device__ __forceinline__ void ldm_x4(unsigned* r, unsigned addr) {
    asm volatile("ldmatrix.sync.aligned.m8n8.x4.shared.b16 {%0,%1,%2,%3}, [%4];"
        : "=r"(r[0]), "=r"(r[1]), "=r"(r[2]), "=r"(r[3]) : "r"(addr));
}
__device__ __forceinline__ void ldm_x2(unsigned* r, unsigned addr) {
    asm volatile("ldmatrix.sync.aligned.m8n8.x2.shared.b16 {%0,%1}, [%2];"
        : "=r"(r[0]), "=r"(r[1]) : "r"(addr));
}

// ---------------- index dtype detection -------------------------------------
__global__ void k_detect_nid(const int* __restrict__ p) {
    int v = p[1 + 2 * threadIdx.x];
    int any = __syncthreads_or(v != 0);
    if (threadIdx.x == 0) g_nid64 = (any == 0) ? 1 : 0;
}
__global__ void k_detect_ei(const int* __restrict__ p) {
    int v = p[1 + 2 * threadIdx.x];
    int any = __syncthreads_or(v != 0);
    if (threadIdx.x == 0) g_ei64 = (any == 0) ? 1 : 0;
}

// ---------------- gather x = memory_table[n_id] -> bf16 hi/lo ---------------
__global__ void k_gather(const float* __restrict__ mem, const void* __restrict__ n_id, int N) {
    int idx = blockIdx.x * blockDim.x + threadIdx.x;
    if (idx >= N * 64) return;
    int i = idx >> 6, c2 = idx & 63;
    int node = ld_idx(n_id, i, g_nid64);
    float2 v = ((const float2*)(mem + (size_t)node * D))[c2];
    __nv_bfloat16 h0, l0, h1, l1;
    split_bf(v.x, h0, l0);
    split_bf(v.y, h1, l1);
    ((__nv_bfloat162*)g_xhi)[(size_t)i * 64 + c2] = __halves2bfloat162(h0, h1);
    ((__nv_bfloat162*)g_xlo)[(size_t)i * 64 + c2] = __halves2bfloat162(l0, l1);
}

// ---------------- pe -> bf16 hi/lo, coalesced via smem staging --------------
// block = 256 thr handles 32 edges
__global__ __launch_bounds__(256) void k_prep_pe(const float* __restrict__ ea,
                                                 const float* __restrict__ et, int E) {
    __shared__ float sea[32][68];
    __shared__ float set[32];
    int e0 = blockIdx.x * 32;
    int tid = threadIdx.x;
    for (int i = tid; i < 32 * 66; i += 256) {
        int r = i / 66, c = i - r * 66;
        sea[r][c] = (e0 + r < E) ? ea[(size_t)(e0 + r) * 66 + c] : 0.f;
    }
    if (tid < 32) set[tid] = et[tid];
    __syncthreads();
    for (int i = tid; i < 32 * 40; i += 256) {
        int r = i / 40, w = i - r * 40;
        if (e0 + r >= E) break;
        float v0, v1;
        int t = (int)sea[r][3];
#pragma unroll
        for (int u = 0; u < 2; u++) {
            int k = 2 * w + u;
            float val = 0.f;
            if (k < 3)       val = sea[r][k];
            else if (k < 65) val = sea[r][k + 1];
            else if (k < 73) val = set[t * 8 + (k - 65)];
            if (u == 0) v0 = val; else v1 = val;
        }
        __nv_bfloat16 h0, l0, h1, l1;
        split_bf(v0, h0, l0);
        split_bf(v1, h1, l1);
        size_t o = (size_t)(e0 + r) * 40 + w;
        ((__nv_bfloat162*)g_pehi)[o] = __halves2bfloat162(h0, h1);
        ((__nv_bfloat162*)g_pelo)[o] = __halves2bfloat162(l0, l1);
    }
}

// ---------------- transpose + split all weights -----------------------------
__global__ void k_split_w(
    const float* __restrict__ Wq1, const float* __restrict__ Wk1,
    const float* __restrict__ Wv1, const float* __restrict__ Ws1,
    const float* __restrict__ Wq2, const float* __restrict__ Wk2,
    const float* __restrict__ Wv2, const float* __restrict__ Ws2,
    const float* __restrict__ We1, const float* __restrict__ We2)
{
    const float* tab[8] = {Wq1, Wk1, Wv1, Ws1, Wq2, Wk2, Wv2, Ws2};
    const float* tabe[2] = {We1, We2};
    int idx = blockIdx.x * blockDim.x + threadIdx.x;
    const int NODE_TOT = 2 * 4 * D * D;
    if (idx < NODE_TOT) {
        int layer = idx / (4 * D * D);
        int rem = idx % (4 * D * D);
        int w = rem / (D * D);
        int rem2 = rem % (D * D);
        int n = rem2 / D, k = rem2 % D;
        float v = tab[layer * 4 + w][k * D + n];
        __nv_bfloat16 h, l;
        split_bf(v, h, l);
        g_wnhi[layer][w][n * D + k] = h;
        g_wnlo[layer][w][n * D + k] = l;
    } else if (idx < NODE_TOT + 2 * D * KE) {
        int r = idx - NODE_TOT;
        int layer = r / (D * KE);
        int rem = r % (D * KE);
        int n = rem / KE, k = rem % KE;
        float v = (k < 73) ? tabe[layer][k * D + n] : 0.f;
        __nv_bfloat16 h, l;
        split_bf(v, h, l);
        g_wehi[layer][n * KE + k] = h;
        g_welo[layer][n * KE + k] = l;
    }
}

// ---------------- node GEMM (smem-staged bf16x3 mma) ------------------------
// block 256 = 8 warps (4 m-groups x 2 n-groups); BM=128, BN=128, K=128
__global__ __launch_bounds__(256) void k_ngemm(int layer, int M,
    const float* __restrict__ bq, const float* __restrict__ bk,
    const float* __restrict__ bv, const float* __restrict__ bs)
{
    extern __shared__ unsigned char smraw[];
    __nv_bfloat16* sAh = (__nv_bfloat16*)smraw;
    __nv_bfloat16* sAl = sAh + 128 * NSTR;
    __nv_bfloat16* sBh = sAl + 128 * NSTR;
    __nv_bfloat16* sBl = sBh + 128 * NSTR;
    int tid = threadIdx.x, lane = tid & 31, wid = tid >> 5;
    int wm = wid & 3, wn = wid >> 2;
    int m0 = blockIdx.x * 128;

    // stage A (hi/lo) as u32 words: row r, 64 words
    {
        const unsigned* Ah = (const unsigned*)g_xhi;
        const unsigned* Al = (const unsigned*)g_xlo;
        unsigned* dAh = (unsigned*)sAh;
        unsigned* dAl = (unsigned*)sAl;
        for (int i = tid; i < 128 * 64; i += 256) {
            int r = i >> 6, w = i & 63;
            bool ok = (m0 + r) < M;
            dAh[r * 68 + w] = ok ? Ah[(size_t)(m0 + r) * 64 + w] : 0u;
            dAl[r * 68 + w] = ok ? Al[(size_t)(m0 + r) * 64 + w] : 0u;
        }
    }
    unsigned aBH = (unsigned)__cvta_generic_to_shared(sAh);
    unsigned aBL = (unsigned)__cvta_generic_to_shared(sAl);
    unsigned bBH = (unsigned)__cvta_generic_to_shared(sBh);
    unsigned bBL = (unsigned)__cvta_generic_to_shared(sBl);

    const float* bias[4] = {bq, bk, bv, bs};
    float* Cp[4] = {g_q, g_k, g_v, g_s};

    for (int w = 0; w < 4; w++) {
        __syncthreads();   // prior compute done before overwriting B
        {
            const unsigned* Bh = (const unsigned*)g_wnhi[layer][w];
            const unsigned* Bl = (const unsigned*)g_wnlo[layer][w];
            unsigned* dBh = (unsigned*)sBh;
            unsigned* dBl = (unsigned*)sBl;
            for (int i = tid; i < 128 * 64; i += 256) {
                int r = i >> 6, c = i & 63;
                dBh[r * 68 + c] = Bh[r * 64 + c];
                dBl[r * 68 + c] = Bl[r * 64 + c];
            }
        }
        __syncthreads();

        float acc[2][8][4];
#pragma unroll
        for (int mt = 0; mt < 2; mt++)
#pragma unroll
            for (int nt = 0; nt < 8; nt++)
#pragma unroll
                for (int c = 0; c < 4; c++) acc[mt][nt][c] = 0.f;

        for (int ks = 0; ks < 8; ks++) {
            unsigned kb = ks * 32;
            unsigned ah[2][4], al[2][4];
#pragma unroll
            for (int mt = 0; mt < 2; mt++) {
                unsigned rowA = 32 * wm + 16 * mt + (lane & 15);
                unsigned off = rowA * (NSTR * 2) + kb + ((lane >> 4) << 4);
                ldm_x4(ah[mt], aBH + off);
                ldm_x4(al[mt], aBL + off);
            }
            unsigned bh[8][2], bl[8][2];
#pragma unroll
            for (int nt = 0; nt < 8; nt++) {
                unsigned rowB = 64 * wn + 8 * nt + (lane & 7);
                unsigned off = rowB * (NSTR * 2) + kb + (((lane >> 3) & 1) << 4);
                ldm_x2(bh[nt], bBH + off);
                ldm_x2(bl[nt], bBL + off);
            }
            // pass 1: Ah*Bh
#pragma unroll
            for (int nt = 0; nt < 8; nt++)
#pragma unroll
                for (int mt = 0; mt < 2; mt++)
                    mma_bf16(acc[mt][nt], ah[mt], bh[nt][0], bh[nt][1]);
            // pass 2: Al*Bh
#pragma unroll
            for (int nt = 0; nt < 8; nt++)
#pragma unroll
                for (int mt = 0; mt < 2; mt++)
                    mma_bf16(acc[mt][nt], al[mt], bh[nt][0], bh[nt][1]);
            // pass 3: Ah*Bl
#pragma unroll
            for (int nt = 0; nt < 8; nt++)
#pragma unroll
                for (int mt = 0; mt < 2; mt++)
                    mma_bf16(acc[mt][nt], ah[mt], bl[nt][0], bl[nt][1]);
        }
        // epilogue
#pragma unroll
        for (int nt = 0; nt < 8; nt++) {
            int n = 64 * wn + 8 * nt + (lane & 3) * 2;
            float b0 = bias[w][n], b1 = bias[w][n + 1];
#pragma unroll
            for (int mt = 0; mt < 2; mt++) {
                int r = m0 + 32 * wm + 16 * mt + (lane >> 2);
                if (r < M) {
                    float2 o = make_float2(acc[mt][nt][0] + b0, acc[mt][nt][1] + b1);
                    *(float2*)(Cp[w] + (size_t)r * D + n) = o;
                }
                if (r + 8 < M) {
                    float2 o = make_float2(acc[mt][nt][2] + b0, acc[mt][nt][3] + b1);
                    *(float2*)(Cp[w] + (size_t)(r + 8) * D + n) = o;
                }
            }
        }
    }
}

// ---------------- edge GEMM (smem-staged bf16x3 mma): e = pe @ We -----------
__global__ __launch_bounds__(256) void k_egemm(int layer, int E) {
    extern __shared__ unsigned char smraw[];
    __nv_bfloat16* sAh = (__nv_bfloat16*)smraw;
    __nv_bfloat16* sAl = sAh + 128 * ESTR;
    __nv_bfloat16* sBh = sAl + 128 * ESTR;
    __nv_bfloat16* sBl = sBh + 128 * ESTR;
    int tid = threadIdx.x, lane = tid & 31, wid = tid >> 5;
    int wm = wid & 3, wn = wid >> 2;
    int m0 = blockIdx.x * 128;

    {
        const unsigned* Ah = (const unsigned*)g_pehi;
        const unsigned* Al = (const unsigned*)g_pelo;
        const unsigned* Bh = (const unsigned*)g_wehi[layer];
        const unsigned* Bl = (const unsigned*)g_welo[layer];
        unsigned* dAh = (unsigned*)sAh;
        unsigned* dAl = (unsigned*)sAl;
        unsigned* dBh = (unsigned*)sBh;
        unsigned* dBl = (unsigned*)sBl;
        for (int i = tid; i < 128 * 40; i += 256) {
            int r = i / 40, w = i - r * 40;
            bool ok = (m0 + r) < E;
            dAh[r * 44 + w] = ok ? Ah[(size_t)(m0 + r) * 40 + w] : 0u;
            dAl[r * 44 + w] = ok ? Al[(size_t)(m0 + r) * 40 + w] : 0u;
            dBh[r * 44 + w] = Bh[r * 40 + w];
            dBl[r * 44 + w] = Bl[r * 40 + w];
        }
    }
    __syncthreads();
    unsigned aBH = (unsigned)__cvta_generic_to_shared(sAh);
    unsigned aBL = (unsigned)__cvta_generic_to_shared(sAl);
    unsigned bBH = (unsigned)__cvta_generic_to_shared(sBh);
    unsigned bBL = (unsigned)__cvta_generic_to_shared(sBl);

    float acc[2][8][4];
#pragma unroll
    for (int mt = 0; mt < 2; mt++)
#pragma unroll
        for (int nt = 0; nt < 8; nt++)
#pragma unroll
            for (int c = 0; c < 4; c++) acc[mt][nt][c] = 0.f;

    for (int ks = 0; ks < 5; ks++) {
        unsigned kb = ks * 32;
        unsigned ah[2][4], al[2][4];
#pragma unroll
        for (int mt = 0; mt < 2; mt++) {
            unsigned rowA = 32 * wm + 16 * mt + (lane & 15);
            unsigned off = rowA * (ESTR * 2) + kb + ((lane >> 4) << 4);
            ldm_x4(ah[mt], aBH + off);
            ldm_x4(al[mt], aBL + off);
        }
        unsigned bh[8][2], bl[8][2];
#pragma unroll
        for (int nt = 0; nt < 8; nt++) {
            unsigned rowB = 64 * wn + 8 * nt + (lane & 7);
            unsigned off = rowB * (ESTR * 2) + kb + (((lane >> 3) & 1) << 4);
            ldm_x2(bh[nt], bBH + off);
            ldm_x2(bl[nt], bBL + off);
        }
#pragma unroll
        for (int nt = 0; nt < 8; nt++)
#pragma unroll
            for (int mt = 0; mt < 2; mt++)
                mma_bf16(acc[mt][nt], ah[mt], bh[nt][0], bh[nt][1]);
#pragma unroll
        for (int nt = 0; nt < 8; nt++)
#pragma unroll
            for (int mt = 0; mt < 2; mt++)
                mma_bf16(acc[mt][nt], al[mt], bh[nt][0], bh[nt][1]);
#pragma unroll
        for (int nt = 0; nt < 8; nt++)
#pragma unroll
            for (int mt = 0; mt < 2; mt++)
                mma_bf16(acc[mt][nt], ah[mt], bl[nt][0], bl[nt][1]);
    }
#pragma unroll
    for (int nt = 0; nt < 8; nt++) {
        int n = 64 * wn + 8 * nt + (lane & 3) * 2;
#pragma unroll
        for (int mt = 0; mt < 2; mt++) {
            int r = m0 + 32 * wm + 16 * mt + (lane >> 2);
            if (r < E) {
                float2 o = make_float2(acc[mt][nt][0], acc[mt][nt][1]);
                *(float2*)(g_e + (size_t)r * D + n) = o;
            }
            if (r + 8 < E) {
                float2 o = make_float2(acc[mt][nt][2], acc[mt][nt][3]);
                *(float2*)(g_e + (size_t)(r + 8) * D + n) = o;
            }
        }
    }
}

// ---------------- per-layer init: agg=0, den=0, m=-inf ----------------------
__global__ void k_init(int N) {
    int idx = blockIdx.x * blockDim.x + threadIdx.x;
    if (idx < N * D) g_agg[idx] = 0.f;
    if (idx < N * 4) { g_den[idx] = 0.f; g_m[idx] = INT_MIN; }
}

// ---------------- scores + segment max (warp per edge) ----------------------
__global__ void k_score(const void* __restrict__ ei, int E) {
    int gt = blockIdx.x * blockDim.x + threadIdx.x;
    int ed = gt >> 5;
    if (ed >= E) return;
    int lane = gt & 31;
    int is64 = g_ei64;
    int src = ld_idx(ei, ed, is64);
    int dst = ld_idx(ei, (long long)E + ed, is64);
    float4 q  = ((const float4*)(g_q + (size_t)dst * D))[lane];
    float4 kk = ((const float4*)(g_k + (size_t)src * D))[lane];
    float4 ev = ((const float4*)(g_e + (size_t)ed  * D))[lane];
    float s = q.x * (kk.x + ev.x) + q.y * (kk.y + ev.y)
            + q.z * (kk.z + ev.z) + q.w * (kk.w + ev.w);
    s += __shfl_xor_sync(0xffffffffu, s, 1);
    s += __shfl_xor_sync(0xffffffffu, s, 2);
    s += __shfl_xor_sync(0xffffffffu, s, 4);
    if ((lane & 7) == 0) {
        int h = lane >> 3;
        float sc = s * 0.1767766953f;
        g_score[ed * 4 + h] = sc;
        atomicMax(&g_m[dst * 4 + h], fkey(sc));
    }
}

// ---------------- exp(score - m) + segment denom ----------------------------
__global__ void k_ex(const void* __restrict__ ei, int E) {
    int idx = blockIdx.x * blockDim.x + threadIdx.x;
    if (idx >= E * 4) return;
    int ed = idx >> 2, h = idx & 3;
    int dst = ld_idx(ei, (long long)E + ed, g_ei64);
    float mm = fdecode(g_m[dst * 4 + h]);
    float ex = expf(g_score[idx] - mm);
    g_score[idx] = ex;
    atomicAdd(&g_den[dst * 4 + h], ex);
}

// ---------------- weighted scatter-add of v (vector red) --------------------
__global__ void k_agg(const void* __restrict__ ei, int E) {
    int idx = blockIdx.x * blockDim.x + threadIdx.x;
    if (idx >= E * 32) return;
    int ed = idx >> 5, c4 = idx & 31;
    int is64 = g_ei64;
    int src = ld_idx(ei, ed, is64);
    int dst = ld_idx(ei, (long long)E + ed, is64);
    int h = c4 >> 3;
    float alpha = g_score[ed * 4 + h] / (g_den[dst * 4 + h] + 1e-16f);
    float4 v  = ((const float4*)(g_v + (size_t)src * D))[c4];
    float4 ev = ((const float4*)(g_e + (size_t)ed  * D))[c4];
    float* a = g_agg + (size_t)dst * D + c4 * 4;
    asm volatile("red.global.add.v4.f32 [%0], {%1,%2,%3,%4};"
        :: "l"(a), "f"((v.x + ev.x) * alpha), "f"((v.y + ev.y) * alpha),
           "f"((v.z + ev.z) * alpha), "f"((v.w + ev.w) * alpha) : "memory");
}

// ---------------- out = agg + skip; relu -> bf16 hi/lo x, else -> d_out -----
__global__ void k_final(float* __restrict__ out, int N, int relu) {
    int idx = blockIdx.x * blockDim.x + threadIdx.x;
    if (idx >= N * 32) return;
    int i = idx >> 5, c4 = idx & 31;
    float4 a = ((const float4*)(g_agg + (size_t)i * D))[c4];
    float4 s = ((const float4*)(g_s + (size_t)i * D))[c4];
    float4 o = make_float4(a.x + s.x, a.y + s.y, a.z + s.z, a.w + s.w);
    if (relu) {
        o.x = fmaxf(o.x, 0.f); o.y = fmaxf(o.y, 0.f);
        o.z = fmaxf(o.z, 0.f); o.w = fmaxf(o.w, 0.f);
        __nv_bfloat16 h0, l0, h1, l1, h2, l2, h3, l3;
        split_bf(o.x, h0, l0); split_bf(o.y, h1, l1);
        split_bf(o.z, h2, l2); split_bf(o.w, h3, l3);
        size_t base = (size_t)i * 64 + c4 * 2;
        ((__nv_bfloat162*)g_xhi)[base]     = __halves2bfloat162(h0, h1);
        ((__nv_bfloat162*)g_xhi)[base + 1] = __halves2bfloat162(h2, h3);
        ((__nv_bfloat162*)g_xlo)[base]     = __halves2bfloat162(l0, l1);
        ((__nv_bfloat162*)g_xlo)[base + 1] = __halves2bfloat162(l2, l3);
    } else {
        ((float4*)(out + (size_t)i * D))[c4] = o;
    }
}

// ---------------- launch -----------------------------------------------------
extern "C" void kernel_launch(void* const* d_in, const int* in_sizes, int n_in,
                              void* d_out, int out_size) {
    const float* mem    = (const float*)d_in[0];
    const float* ea     = (const float*)d_in[1];
    const float* et_emb = (const float*)d_in[2];
    const float* W1[5]  = {(const float*)d_in[3], (const float*)d_in[4], (const float*)d_in[5],
                           (const float*)d_in[6], (const float*)d_in[7]};   // Wq,Wk,Wv,We,Ws
    const float* b1[4]  = {(const float*)d_in[8], (const float*)d_in[9],
                           (const float*)d_in[10], (const float*)d_in[11]};
    const float* W2[5]  = {(const float*)d_in[12], (const float*)d_in[13], (const float*)d_in[14],
                           (const float*)d_in[15], (const float*)d_in[16]};
    const float* b2[4]  = {(const float*)d_in[17], (const float*)d_in[18],
                           (const float*)d_in[19], (const float*)d_in[20]};
    const void* n_id = d_in[21];
    const void* ei   = d_in[22];
    float* out = (float*)d_out;

    int N = in_sizes[21];
    int E = in_sizes[22] / 2;
    if (N > NMAX) N = NMAX;
    if (E > EMAX) E = EMAX;

    const int SMEM_N = 4 * 128 * NSTR * 2;  // 139264
    const int SMEM_E = 4 * 128 * ESTR * 2;  // 90112
    cudaFuncSetAttribute(k_ngemm, cudaFuncAttributeMaxDynamicSharedMemorySize, SMEM_N);
    cudaFuncSetAttribute(k_egemm, cudaFuncAttributeMaxDynamicSharedMemorySize, SMEM_E);

    const int T = 256;
    k_detect_nid<<<1, 1024>>>((const int*)n_id);
    k_detect_ei<<<1, 1024>>>((const int*)ei);
    k_gather<<<(N * 64 + T - 1) / T, T>>>(mem, n_id, N);
    k_prep_pe<<<(E + 31) / 32, T>>>(ea, et_emb, E);
    {
        int tot = 2 * 4 * D * D + 2 * D * KE;
        k_split_w<<<(tot + T - 1) / T, T>>>(W1[0], W1[1], W1[2], W1[4],
                                            W2[0], W2[1], W2[2], W2[4],
                                            W1[3], W2[3]);
    }

    int gN = (N + 127) / 128;
    int gE = (E + 127) / 128;

    // ---- layer 1 ----
    k_ngemm<<<gN, 256, SMEM_N>>>(0, N, b1[0], b1[1], b1[2], b1[3]);
    k_egemm<<<gE, 256, SMEM_E>>>(0, E);
    k_init<<<(N * D + T - 1) / T, T>>>(N);
    k_score<<<(E * 32 + T - 1) / T, T>>>(ei, E);
    k_ex<<<(E * 4 + T - 1) / T, T>>>(ei, E);
    k_agg<<<(E * 32 + T - 1) / T, T>>>(ei, E);
    k_final<<<(N * 32 + T - 1) / T, T>>>(out, N, 1);

    // ---- layer 2 ----
    k_ngemm<<<gN, 256, SMEM_N>>>(1, N, b2[0], b2[1], b2[2], b2[3]);
    k_egemm<<<gE, 256, SMEM_E>>>(1, E);
    k_init<<<(N * D + T - 1) / T, T>>>(N);
    k_score<<<(E * 32 + T - 1) / T, T>>>(ei, E);
    k_ex<<<(E * 4 + T - 1) / T, T>>>(ei, E);
    k_agg<<<(E * 32 + T - 1) / T, T>>>(ei, E);
    k_final<<<(N * 32 + T - 1) / T, T>>>(out, N, 0);
}

// round 5
// speedup vs baseline: 1.6816x; 1.1117x over previous
#include <cuda_runtime.h>
#include <cuda_bf16.h>
#include <limits.h>
#include <math.h>

#define NMAX 40000
#define EMAX 320000
#define D 128
#define KE 80            // edge K padded 73 -> 80 (5 k-steps of 16)
#define NSTR 136         // node smem row stride in bf16 (272B)
#define ESTR 88          // edge smem row stride in bf16 (176B)

// ---------------- scratch (device globals; no allocations allowed) ----------
__device__ __nv_bfloat16 g_xhi[NMAX * D], g_xlo[NMAX * D];
__device__ __nv_bfloat16 g_pehi[(size_t)EMAX * KE], g_pelo[(size_t)EMAX * KE];
__device__ __nv_bfloat16 g_wnhi[2][4][D * D], g_wnlo[2][4][D * D];   // [n][k]
__device__ __nv_bfloat16 g_wehi[2][D * KE], g_welo[2][D * KE];       // [n][k]
__device__ float g_q[NMAX * D];
__device__ float g_k[NMAX * D];
__device__ float g_v[NMAX * D];
__device__ float g_s[NMAX * D];
__device__ float g_e[(size_t)EMAX * D];      // CSR-ordered edge conditioning
__device__ int   g_rowptr[NMAX + 1];
__device__ int   g_cnt[NMAX];
__device__ int   g_perm[EMAX];               // CSR slot -> original edge id
__device__ int   g_srcp[EMAX];               // CSR-ordered src node
__device__ int   g_nid64;
__device__ int   g_ei64;

__device__ __forceinline__ int ld_idx(const void* p, long long i, int is64) {
    return is64 ? (int)((const long long*)p)[i] : ((const int*)p)[i];
}
__device__ __forceinline__ void split_bf(float v, __nv_bfloat16& h, __nv_bfloat16& l) {
    h = __float2bfloat16(v);
    l = __float2bfloat16(v - __bfloat162float(h));
}
__device__ __forceinline__ void mma_bf16(float* d, const unsigned* a, unsigned b0, unsigned b1) {
    asm volatile(
        "mma.sync.aligned.m16n8k16.row.col.f32.bf16.bf16.f32 "
        "{%0,%1,%2,%3}, {%4,%5,%6,%7}, {%8,%9}, {%0,%1,%2,%3};"
        : "+f"(d[0]), "+f"(d[1]), "+f"(d[2]), "+f"(d[3])
        : "r"(a[0]), "r"(a[1]), "r"(a[2]), "r"(a[3]), "r"(b0), "r"(b1));
}
__device__ __forceinline__ void ldm_x4(unsigned* r, unsigned addr) {
    asm volatile("ldmatrix.sync.aligned.m8n8.x4.shared.b16 {%0,%1,%2,%3}, [%4];"
        : "=r"(r[0]), "=r"(r[1]), "=r"(r[2]), "=r"(r[3]) : "r"(addr));
}
__device__ __forceinline__ void ldm_x2(unsigned* r, unsigned addr) {
    asm volatile("ldmatrix.sync.aligned.m8n8.x2.shared.b16 {%0,%1}, [%2];"
        : "=r"(r[0]), "=r"(r[1]) : "r"(addr));
}

// ---------------- index dtype detection -------------------------------------
__global__ void k_detect_nid(const int* __restrict__ p) {
    int v = p[1 + 2 * threadIdx.x];
    int any = __syncthreads_or(v != 0);
    if (threadIdx.x == 0) g_nid64 = (any == 0) ? 1 : 0;
}
__global__ void k_detect_ei(const int* __restrict__ p) {
    int v = p[1 + 2 * threadIdx.x];
    int any = __syncthreads_or(v != 0);
    if (threadIdx.x == 0) g_ei64 = (any == 0) ? 1 : 0;
}

// ---------------- CSR build --------------------------------------------------
__global__ void k_zero_cnt(int N) {
    int i = blockIdx.x * blockDim.x + threadIdx.x;
    if (i < N) g_cnt[i] = 0;
}
__global__ void k_hist(const void* __restrict__ ei, int E) {
    int i = blockIdx.x * blockDim.x + threadIdx.x;
    if (i >= E) return;
    int dst = ld_idx(ei, (long long)E + i, g_ei64);
    atomicAdd(&g_cnt[dst], 1);
}
__global__ void k_scan(int N, int E) {
    __shared__ int s[1024];
    int t = threadIdx.x;
    int ch = (N + 1023) >> 10;
    int b = t * ch;
    int sum = 0;
    for (int i = 0; i < ch; i++) { int n = b + i; if (n < N) sum += g_cnt[n]; }
    s[t] = sum;
    __syncthreads();
    for (int off = 1; off < 1024; off <<= 1) {
        int v = (t >= off) ? s[t - off] : 0;
        __syncthreads();
        s[t] += v;
        __syncthreads();
    }
    int base = s[t] - sum;   // exclusive prefix
    for (int i = 0; i < ch; i++) {
        int n = b + i;
        if (n < N) { int c = g_cnt[n]; g_rowptr[n] = base; base += c; g_cnt[n] = 0; }
    }
    if (t == 1023) g_rowptr[N] = E;
}
__global__ void k_permb(const void* __restrict__ ei, int E) {
    int i = blockIdx.x * blockDim.x + threadIdx.x;
    if (i >= E) return;
    int is64 = g_ei64;
    int src = ld_idx(ei, i, is64);
    int dst = ld_idx(ei, (long long)E + i, is64);
    int slot = g_rowptr[dst] + atomicAdd(&g_cnt[dst], 1);
    g_perm[slot] = i;
    g_srcp[slot] = src;
}

// ---------------- gather x = memory_table[n_id] -> bf16 hi/lo ---------------
__global__ void k_gather(const float* __restrict__ mem, const void* __restrict__ n_id, int N) {
    int idx = blockIdx.x * blockDim.x + threadIdx.x;
    if (idx >= N * 64) return;
    int i = idx >> 6, c2 = idx & 63;
    int node = ld_idx(n_id, i, g_nid64);
    float2 v = ((const float2*)(mem + (size_t)node * D))[c2];
    __nv_bfloat16 h0, l0, h1, l1;
    split_bf(v.x, h0, l0);
    split_bf(v.y, h1, l1);
    ((__nv_bfloat162*)g_xhi)[(size_t)i * 64 + c2] = __halves2bfloat162(h0, h1);
    ((__nv_bfloat162*)g_xlo)[(size_t)i * 64 + c2] = __halves2bfloat162(l0, l1);
}

// ---------------- pe -> bf16 hi/lo, coalesced via smem staging --------------
__global__ __launch_bounds__(256) void k_prep_pe(const float* __restrict__ ea,
                                                 const float* __restrict__ et, int E) {
    __shared__ float sea[32][68];
    __shared__ float set[32];
    int e0 = blockIdx.x * 32;
    int tid = threadIdx.x;
    for (int i = tid; i < 32 * 66; i += 256) {
        int r = i / 66, c = i - r * 66;
        sea[r][c] = (e0 + r < E) ? ea[(size_t)(e0 + r) * 66 + c] : 0.f;
    }
    if (tid < 32) set[tid] = et[tid];
    __syncthreads();
    for (int i = tid; i < 32 * 40; i += 256) {
        int r = i / 40, w = i - r * 40;
        if (e0 + r >= E) break;
        float v0, v1;
        int t = (int)sea[r][3];
#pragma unroll
        for (int u = 0; u < 2; u++) {
            int k = 2 * w + u;
            float val = 0.f;
            if (k < 3)       val = sea[r][k];
            else if (k < 65) val = sea[r][k + 1];
            else if (k < 73) val = set[t * 8 + (k - 65)];
            if (u == 0) v0 = val; else v1 = val;
        }
        __nv_bfloat16 h0, l0, h1, l1;
        split_bf(v0, h0, l0);
        split_bf(v1, h1, l1);
        size_t o = (size_t)(e0 + r) * 40 + w;
        ((__nv_bfloat162*)g_pehi)[o] = __halves2bfloat162(h0, h1);
        ((__nv_bfloat162*)g_pelo)[o] = __halves2bfloat162(l0, l1);
    }
}

// ---------------- transpose + split all weights -----------------------------
__global__ void k_split_w(
    const float* __restrict__ Wq1, const float* __restrict__ Wk1,
    const float* __restrict__ Wv1, const float* __restrict__ Ws1,
    const float* __restrict__ Wq2, const float* __restrict__ Wk2,
    const float* __restrict__ Wv2, const float* __restrict__ Ws2,
    const float* __restrict__ We1, const float* __restrict__ We2)
{
    const float* tab[8] = {Wq1, Wk1, Wv1, Ws1, Wq2, Wk2, Wv2, Ws2};
    const float* tabe[2] = {We1, We2};
    int idx = blockIdx.x * blockDim.x + threadIdx.x;
    const int NODE_TOT = 2 * 4 * D * D;
    if (idx < NODE_TOT) {
        int layer = idx / (4 * D * D);
        int rem = idx % (4 * D * D);
        int w = rem / (D * D);
        int rem2 = rem % (D * D);
        int n = rem2 / D, k = rem2 % D;
        float v = tab[layer * 4 + w][k * D + n];
        __nv_bfloat16 h, l;
        split_bf(v, h, l);
        g_wnhi[layer][w][n * D + k] = h;
        g_wnlo[layer][w][n * D + k] = l;
    } else if (idx < NODE_TOT + 2 * D * KE) {
        int r = idx - NODE_TOT;
        int layer = r / (D * KE);
        int rem = r % (D * KE);
        int n = rem / KE, k = rem % KE;
        float v = (k < 73) ? tabe[layer][k * D + n] : 0.f;
        __nv_bfloat16 h, l;
        split_bf(v, h, l);
        g_wehi[layer][n * KE + k] = h;
        g_welo[layer][n * KE + k] = l;
    }
}

// ---------------- node GEMM (smem-staged bf16x3 mma) ------------------------
__global__ __launch_bounds__(256) void k_ngemm(int layer, int M,
    const float* __restrict__ bq, const float* __restrict__ bk,
    const float* __restrict__ bv, const float* __restrict__ bs)
{
    extern __shared__ unsigned char smraw[];
    __nv_bfloat16* sAh = (__nv_bfloat16*)smraw;
    __nv_bfloat16* sAl = sAh + 128 * NSTR;
    __nv_bfloat16* sBh = sAl + 128 * NSTR;
    __nv_bfloat16* sBl = sBh + 128 * NSTR;
    int tid = threadIdx.x, lane = tid & 31, wid = tid >> 5;
    int wm = wid & 3, wn = wid >> 2;
    int m0 = blockIdx.x * 128;

    {
        const unsigned* Ah = (const unsigned*)g_xhi;
        const unsigned* Al = (const unsigned*)g_xlo;
        unsigned* dAh = (unsigned*)sAh;
        unsigned* dAl = (unsigned*)sAl;
        for (int i = tid; i < 128 * 64; i += 256) {
            int r = i >> 6, w = i & 63;
            bool ok = (m0 + r) < M;
            dAh[r * 68 + w] = ok ? Ah[(size_t)(m0 + r) * 64 + w] : 0u;
            dAl[r * 68 + w] = ok ? Al[(size_t)(m0 + r) * 64 + w] : 0u;
        }
    }
    unsigned aBH = (unsigned)__cvta_generic_to_shared(sAh);
    unsigned aBL = (unsigned)__cvta_generic_to_shared(sAl);
    unsigned bBH = (unsigned)__cvta_generic_to_shared(sBh);
    unsigned bBL = (unsigned)__cvta_generic_to_shared(sBl);

    const float* bias[4] = {bq, bk, bv, bs};
    float* Cp[4] = {g_q, g_k, g_v, g_s};

    for (int w = 0; w < 4; w++) {
        __syncthreads();
        {
            const unsigned* Bh = (const unsigned*)g_wnhi[layer][w];
            const unsigned* Bl = (const unsigned*)g_wnlo[layer][w];
            unsigned* dBh = (unsigned*)sBh;
            unsigned* dBl = (unsigned*)sBl;
            for (int i = tid; i < 128 * 64; i += 256) {
                int r = i >> 6, c = i & 63;
                dBh[r * 68 + c] = Bh[r * 64 + c];
                dBl[r * 68 + c] = Bl[r * 64 + c];
            }
        }
        __syncthreads();

        float acc[2][8][4];
#pragma unroll
        for (int mt = 0; mt < 2; mt++)
#pragma unroll
            for (int nt = 0; nt < 8; nt++)
#pragma unroll
                for (int c = 0; c < 4; c++) acc[mt][nt][c] = 0.f;

        for (int ks = 0; ks < 8; ks++) {
            unsigned kb = ks * 32;
            unsigned ah[2][4], al[2][4];
#pragma unroll
            for (int mt = 0; mt < 2; mt++) {
                unsigned rowA = 32 * wm + 16 * mt + (lane & 15);
                unsigned off = rowA * (NSTR * 2) + kb + ((lane >> 4) << 4);
                ldm_x4(ah[mt], aBH + off);
                ldm_x4(al[mt], aBL + off);
            }
            unsigned bh[8][2], bl[8][2];
#pragma unroll
            for (int nt = 0; nt < 8; nt++) {
                unsigned rowB = 64 * wn + 8 * nt + (lane & 7);
                unsigned off = rowB * (NSTR * 2) + kb + (((lane >> 3) & 1) << 4);
                ldm_x2(bh[nt], bBH + off);
                ldm_x2(bl[nt], bBL + off);
            }
#pragma unroll
            for (int nt = 0; nt < 8; nt++)
#pragma unroll
                for (int mt = 0; mt < 2; mt++)
                    mma_bf16(acc[mt][nt], ah[mt], bh[nt][0], bh[nt][1]);
#pragma unroll
            for (int nt = 0; nt < 8; nt++)
#pragma unroll
                for (int mt = 0; mt < 2; mt++)
                    mma_bf16(acc[mt][nt], al[mt], bh[nt][0], bh[nt][1]);
#pragma unroll
            for (int nt = 0; nt < 8; nt++)
#pragma unroll
                for (int mt = 0; mt < 2; mt++)
                    mma_bf16(acc[mt][nt], ah[mt], bl[nt][0], bl[nt][1]);
        }
#pragma unroll
        for (int nt = 0; nt < 8; nt++) {
            int n = 64 * wn + 8 * nt + (lane & 3) * 2;
            float b0 = bias[w][n], b1 = bias[w][n + 1];
#pragma unroll
            for (int mt = 0; mt < 2; mt++) {
                int r = m0 + 32 * wm + 16 * mt + (lane >> 2);
                if (r < M) {
                    float2 o = make_float2(acc[mt][nt][0] + b0, acc[mt][nt][1] + b1);
                    *(float2*)(Cp[w] + (size_t)r * D + n) = o;
                }
                if (r + 8 < M) {
                    float2 o = make_float2(acc[mt][nt][2] + b0, acc[mt][nt][3] + b1);
                    *(float2*)(Cp[w] + (size_t)(r + 8) * D + n) = o;
                }
            }
        }
    }
}

// ---------------- edge GEMM (perm-gathered A, CSR-ordered output) -----------
__global__ __launch_bounds__(256) void k_egemm(int layer, int E) {
    extern __shared__ unsigned char smraw[];
    __nv_bfloat16* sAh = (__nv_bfloat16*)smraw;
    __nv_bfloat16* sAl = sAh + 128 * ESTR;
    __nv_bfloat16* sBh = sAl + 128 * ESTR;
    __nv_bfloat16* sBl = sBh + 128 * ESTR;
    __shared__ int sperm[128];
    int tid = threadIdx.x, lane = tid & 31, wid = tid >> 5;
    int wm = wid & 3, wn = wid >> 2;
    int m0 = blockIdx.x * 128;

    if (tid < 128) sperm[tid] = (m0 + tid < E) ? g_perm[m0 + tid] : 0;
    __syncthreads();
    {
        const unsigned* Ah = (const unsigned*)g_pehi;
        const unsigned* Al = (const unsigned*)g_pelo;
        const unsigned* Bh = (const unsigned*)g_wehi[layer];
        const unsigned* Bl = (const unsigned*)g_welo[layer];
        unsigned* dAh = (unsigned*)sAh;
        unsigned* dAl = (unsigned*)sAl;
        unsigned* dBh = (unsigned*)sBh;
        unsigned* dBl = (unsigned*)sBl;
        for (int i = tid; i < 128 * 40; i += 256) {
            int r = i / 40, w = i - r * 40;
            bool ok = (m0 + r) < E;
            size_t pr = (size_t)sperm[r] * 40 + w;
            dAh[r * 44 + w] = ok ? Ah[pr] : 0u;
            dAl[r * 44 + w] = ok ? Al[pr] : 0u;
            dBh[r * 44 + w] = Bh[r * 40 + w];
            dBl[r * 44 + w] = Bl[r * 40 + w];
        }
    }
    __syncthreads();
    unsigned aBH = (unsigned)__cvta_generic_to_shared(sAh);
    unsigned aBL = (unsigned)__cvta_generic_to_shared(sAl);
    unsigned bBH = (unsigned)__cvta_generic_to_shared(sBh);
    unsigned bBL = (unsigned)__cvta_generic_to_shared(sBl);

    float acc[2][8][4];
#pragma unroll
    for (int mt = 0; mt < 2; mt++)
#pragma unroll
        for (int nt = 0; nt < 8; nt++)
#pragma unroll
            for (int c = 0; c < 4; c++) acc[mt][nt][c] = 0.f;

    for (int ks = 0; ks < 5; ks++) {
        unsigned kb = ks * 32;
        unsigned ah[2][4], al[2][4];
#pragma unroll
        for (int mt = 0; mt < 2; mt++) {
            unsigned rowA = 32 * wm + 16 * mt + (lane & 15);
            unsigned off = rowA * (ESTR * 2) + kb + ((lane >> 4) << 4);
            ldm_x4(ah[mt], aBH + off);
            ldm_x4(al[mt], aBL + off);
        }
        unsigned bh[8][2], bl[8][2];
#pragma unroll
        for (int nt = 0; nt < 8; nt++) {
            unsigned rowB = 64 * wn + 8 * nt + (lane & 7);
            unsigned off = rowB * (ESTR * 2) + kb + (((lane >> 3) & 1) << 4);
            ldm_x2(bh[nt], bBH + off);
            ldm_x2(bl[nt], bBL + off);
        }
#pragma unroll
        for (int nt = 0; nt < 8; nt++)
#pragma unroll
            for (int mt = 0; mt < 2; mt++)
                mma_bf16(acc[mt][nt], ah[mt], bh[nt][0], bh[nt][1]);
#pragma unroll
        for (int nt = 0; nt < 8; nt++)
#pragma unroll
            for (int mt = 0; mt < 2; mt++)
                mma_bf16(acc[mt][nt], al[mt], bh[nt][0], bh[nt][1]);
#pragma unroll
        for (int nt = 0; nt < 8; nt++)
#pragma unroll
            for (int mt = 0; mt < 2; mt++)
                mma_bf16(acc[mt][nt], ah[mt], bl[nt][0], bl[nt][1]);
    }
#pragma unroll
    for (int nt = 0; nt < 8; nt++) {
        int n = 64 * wn + 8 * nt + (lane & 3) * 2;
#pragma unroll
        for (int mt = 0; mt < 2; mt++) {
            int r = m0 + 32 * wm + 16 * mt + (lane >> 2);
            if (r < E) {
                float2 o = make_float2(acc[mt][nt][0], acc[mt][nt][1]);
                *(float2*)(g_e + (size_t)r * D + n) = o;
            }
            if (r + 8 < E) {
                float2 o = make_float2(acc[mt][nt][2], acc[mt][nt][3]);
                *(float2*)(g_e + (size_t)(r + 8) * D + n) = o;
            }
        }
    }
}

// ---------------- fused attention: online softmax, warp per dst node --------
__global__ __launch_bounds__(256) void k_attn(float* __restrict__ out, int N, int relu) {
    int lane = threadIdx.x & 31;
    int n = blockIdx.x * 8 + (threadIdx.x >> 5);
    if (n >= N) return;
    int beg = g_rowptr[n], end = g_rowptr[n + 1];
    float4 q = ((const float4*)g_q)[(size_t)n * 32 + lane];
    float m = -INFINITY, dsum = 0.f;
    float4 acc = make_float4(0.f, 0.f, 0.f, 0.f);

    for (int e = beg; e < end; e++) {
        int src = g_srcp[e];
        float4 k4 = ((const float4*)g_k)[(size_t)src * 32 + lane];
        float4 e4 = ((const float4*)g_e)[(size_t)e * 32 + lane];
        float4 v4 = ((const float4*)g_v)[(size_t)src * 32 + lane];
        float s = q.x * (k4.x + e4.x) + q.y * (k4.y + e4.y)
                + q.z * (k4.z + e4.z) + q.w * (k4.w + e4.w);
        s += __shfl_xor_sync(0xffffffffu, s, 1);
        s += __shfl_xor_sync(0xffffffffu, s, 2);
        s += __shfl_xor_sync(0xffffffffu, s, 4);
        s *= 0.1767766953f;                      // 1/sqrt(32)
        float mn = fmaxf(m, s);
        float scale = expf(m - mn);              // 0 when m = -inf
        float w = expf(s - mn);
        dsum = dsum * scale + w;
        acc.x = acc.x * scale + w * (v4.x + e4.x);
        acc.y = acc.y * scale + w * (v4.y + e4.y);
        acc.z = acc.z * scale + w * (v4.z + e4.z);
        acc.w = acc.w * scale + w * (v4.w + e4.w);
        m = mn;
    }
    float inv = (dsum > 0.f) ? 1.f / (dsum + 1e-16f) : 0.f;
    float4 s4 = ((const float4*)g_s)[(size_t)n * 32 + lane];
    float4 o = make_float4(acc.x * inv + s4.x, acc.y * inv + s4.y,
                           acc.z * inv + s4.z, acc.w * inv + s4.w);
    if (relu) {
        o.x = fmaxf(o.x, 0.f); o.y = fmaxf(o.y, 0.f);
        o.z = fmaxf(o.z, 0.f); o.w = fmaxf(o.w, 0.f);
        __nv_bfloat16 h0, l0, h1, l1, h2, l2, h3, l3;
        split_bf(o.x, h0, l0); split_bf(o.y, h1, l1);
        split_bf(o.z, h2, l2); split_bf(o.w, h3, l3);
        size_t base = (size_t)n * 64 + lane * 2;
        ((__nv_bfloat162*)g_xhi)[base]     = __halves2bfloat162(h0, h1);
        ((__nv_bfloat162*)g_xhi)[base + 1] = __halves2bfloat162(h2, h3);
        ((__nv_bfloat162*)g_xlo)[base]     = __halves2bfloat162(l0, l1);
        ((__nv_bfloat162*)g_xlo)[base + 1] = __halves2bfloat162(l2, l3);
    } else {
        ((float4*)out)[(size_t)n * 32 + lane] = o;
    }
}

// ---------------- launch -----------------------------------------------------
extern "C" void kernel_launch(void* const* d_in, const int* in_sizes, int n_in,
                              void* d_out, int out_size) {
    const float* mem    = (const float*)d_in[0];
    const float* ea     = (const float*)d_in[1];
    const float* et_emb = (const float*)d_in[2];
    const float* W1[5]  = {(const float*)d_in[3], (const float*)d_in[4], (const float*)d_in[5],
                           (const float*)d_in[6], (const float*)d_in[7]};   // Wq,Wk,Wv,We,Ws
    const float* b1[4]  = {(const float*)d_in[8], (const float*)d_in[9],
                           (const float*)d_in[10], (const float*)d_in[11]};
    const float* W2[5]  = {(const float*)d_in[12], (const float*)d_in[13], (const float*)d_in[14],
                           (const float*)d_in[15], (const float*)d_in[16]};
    const float* b2[4]  = {(const float*)d_in[17], (const float*)d_in[18],
                           (const float*)d_in[19], (const float*)d_in[20]};
    const void* n_id = d_in[21];
    const void* ei   = d_in[22];
    float* out = (float*)d_out;

    int N = in_sizes[21];
    int E = in_sizes[22] / 2;
    if (N > NMAX) N = NMAX;
    if (E > EMAX) E = EMAX;

    const int SMEM_N = 4 * 128 * NSTR * 2;  // 139264
    const int SMEM_E = 4 * 128 * ESTR * 2;  // 90112
    cudaFuncSetAttribute(k_ngemm, cudaFuncAttributeMaxDynamicSharedMemorySize, SMEM_N);
    cudaFuncSetAttribute(k_egemm, cudaFuncAttributeMaxDynamicSharedMemorySize, SMEM_E);

    const int T = 256;
    k_detect_nid<<<1, 1024>>>((const int*)n_id);
    k_detect_ei<<<1, 1024>>>((const int*)ei);
    k_gather<<<(N * 64 + T - 1) / T, T>>>(mem, n_id, N);
    k_prep_pe<<<(E + 31) / 32, T>>>(ea, et_emb, E);
    {
        int tot = 2 * 4 * D * D + 2 * D * KE;
        k_split_w<<<(tot + T - 1) / T, T>>>(W1[0], W1[1], W1[2], W1[4],
                                            W2[0], W2[1], W2[2], W2[4],
                                            W1[3], W2[3]);
    }
    // CSR build
    k_zero_cnt<<<(N + T - 1) / T, T>>>(N);
    k_hist<<<(E + T - 1) / T, T>>>(ei, E);
    k_scan<<<1, 1024>>>(N, E);
    k_permb<<<(E + T - 1) / T, T>>>(ei, E);

    int gN = (N + 127) / 128;
    int gE = (E + 127) / 128;
    int gA = (N + 7) / 8;

    // ---- layer 1 ----
    k_ngemm<<<gN, 256, SMEM_N>>>(0, N, b1[0], b1[1], b1[2], b1[3]);
    k_egemm<<<gE, 256, SMEM_E>>>(0, E);
    k_attn<<<gA, 256>>>(out, N, 1);   // relu -> g_xhi/g_xlo

    // ---- layer 2 ----
    k_ngemm<<<gN, 256, SMEM_N>>>(1, N, b2[0], b2[1], b2[2], b2[3]);
    k_egemm<<<gE, 256, SMEM_E>>>(1, E);
    k_attn<<<gA, 256>>>(out, N, 0);   // -> d_out
}